// round 16
// baseline (speedup 1.0000x reference)
#include <cuda_runtime.h>
#include <cuda_bf16.h>
#include <cuda_fp16.h>

// ----------------------------------------------------------------------------
// RelativeAttention2d  (B=16, C=256, H=32 -> N=1024, HEADS=8, HS=32)
// Round: f16x2 MUFU softmax (h2exp2), denominators via ones-MMA,
//        Q pre-scaled by 0.0625*log2e in GEMM epilogue, V stored fp16.
// ----------------------------------------------------------------------------

namespace {
constexpr int BATCH = 16;
constexpr int PB    = 256 * 1024;
constexpr int HSZ   = BATCH * 8 * 32 * 1024;   // per-tensor head-layout elems
}

typedef unsigned int u32;

__device__ __nv_bfloat16 g_xnb[BATCH * PB];            // LN out  [16384][256]
__device__ __nv_bfloat16 g_ob [BATCH * PB];            // attn out [16384][256]
__device__ __nv_bfloat16 g_qkv[3 * HSZ];               // q,k bf16 | v fp16
__device__ __nv_bfloat16 g_wb[4 * 256 * 256];          // bf16 weights q,k,v,o
__device__ float         g_b3[768];                    // packed bq|bk|bv

// ------------------------------- helpers ------------------------------------
__device__ __forceinline__ u32 bf2(float a, float b) {
    __nv_bfloat162 t = __floats2bfloat162_rn(a, b);
    return *(u32*)&t;
}
__device__ __forceinline__ u32 hf2(float a, float b) {
    __half2 t = __floats2half2_rn(a, b);
    return *(u32*)&t;
}
__device__ __forceinline__ u32 pk2(const __nv_bfloat16* lo, const __nv_bfloat16* hi) {
    return (u32)*(const unsigned short*)lo | ((u32)*(const unsigned short*)hi << 16);
}
__device__ __forceinline__ void mma_bf16(float& c0, float& c1, float& c2, float& c3,
                                         u32 a0, u32 a1, u32 a2, u32 a3,
                                         u32 b0, u32 b1) {
    asm volatile(
        "mma.sync.aligned.m16n8k16.row.col.f32.bf16.bf16.f32 "
        "{%0,%1,%2,%3}, {%4,%5,%6,%7}, {%8,%9}, {%0,%1,%2,%3};"
        : "+f"(c0), "+f"(c1), "+f"(c2), "+f"(c3)
        : "r"(a0), "r"(a1), "r"(a2), "r"(a3), "r"(b0), "r"(b1));
}
__device__ __forceinline__ void mma_f16(float& c0, float& c1, float& c2, float& c3,
                                        u32 a0, u32 a1, u32 a2, u32 a3,
                                        u32 b0, u32 b1) {
    asm volatile(
        "mma.sync.aligned.m16n8k16.row.col.f32.f16.f16.f32 "
        "{%0,%1,%2,%3}, {%4,%5,%6,%7}, {%8,%9}, {%0,%1,%2,%3};"
        : "+f"(c0), "+f"(c1), "+f"(c2), "+f"(c3)
        : "r"(a0), "r"(a1), "r"(a2), "r"(a3), "r"(b0), "r"(b1));
}
__device__ __forceinline__ void ldsm4(u32& r0, u32& r1, u32& r2, u32& r3,
                                      const __nv_bfloat16* p) {
    u32 a = (u32)__cvta_generic_to_shared(p);
    asm volatile("ldmatrix.sync.aligned.m8n8.x4.shared.b16 {%0,%1,%2,%3}, [%4];"
                 : "=r"(r0), "=r"(r1), "=r"(r2), "=r"(r3) : "r"(a));
}
__device__ __forceinline__ void ldsm4t(u32& r0, u32& r1, u32& r2, u32& r3,
                                       const __nv_bfloat16* p) {
    u32 a = (u32)__cvta_generic_to_shared(p);
    asm volatile("ldmatrix.sync.aligned.m8n8.x4.trans.shared.b16 {%0,%1,%2,%3}, [%4];"
                 : "=r"(r0), "=r"(r1), "=r"(r2), "=r"(r3) : "r"(a));
}
__device__ __forceinline__ void cp16(u32 dst, const void* src) {
    asm volatile("cp.async.cg.shared.global [%0], [%1], 16;" :: "r"(dst), "l"(src));
}
#define CP_COMMIT()  asm volatile("cp.async.commit_group;")
#define CP_WAIT1()   asm volatile("cp.async.wait_group 1;")
#define CP_WAIT0()   asm volatile("cp.async.wait_group 0;")

// Q pre-scale: 1/sqrt(256) folded with log2(e) so softmax uses exp2 directly.
#define QSCALE 0.0901941142223433f

// ------------------------------ LayerNorm (-> bf16) --------------------------
__global__ __launch_bounds__(256) void ln_kernel(const float* __restrict__ x,
                                                 const float* __restrict__ gamma,
                                                 const float* __restrict__ beta) {
    __shared__ float sg[256];
    __shared__ float sb[256];
    const int tid = threadIdx.x;
    sg[tid] = gamma[tid];
    sb[tid] = beta[tid];
    __syncthreads();

    const int b = blockIdx.y;
    const int p = blockIdx.x * 256 + tid;
    const float* xb = x + b * PB;

    float s = 0.f, ss = 0.f;
#pragma unroll 32
    for (int c = 0; c < 256; c++) {
        const float v = xb[c * 1024 + p];
        s += v;
        ss += v * v;
    }
    const float mu  = s * (1.0f / 256.0f);
    const float var = ss * (1.0f / 256.0f) - mu * mu;
    const float r   = rsqrtf(var + 1e-5f);

    __nv_bfloat16* ob = g_xnb + (size_t)b * PB;
#pragma unroll 32
    for (int c = 0; c < 256; c++) {
        const float v = xb[c * 1024 + p];
        ob[c * 1024 + p] = __float2bfloat16((v - mu) * r * sg[c] + sb[c]);
    }
}

// ---------------- weight fp32->bf16 + bias packing ---------------------------
__global__ __launch_bounds__(256) void cvt_kernel(const float* __restrict__ w0,
                                                  const float* __restrict__ w1,
                                                  const float* __restrict__ w2,
                                                  const float* __restrict__ w3) {
    const float* src = (blockIdx.y == 0) ? w0 : (blockIdx.y == 1) ? w1
                     : (blockIdx.y == 2) ? w2 : w3;
    __nv_bfloat16* dst = g_wb + (size_t)blockIdx.y * 65536;
    const int i = (blockIdx.x * 256 + threadIdx.x) * 4;
    const float4 v = *(const float4*)&src[i];
    uint2 st;
    st.x = bf2(v.x, v.y);
    st.y = bf2(v.z, v.w);
    *(uint2*)&dst[i] = st;
}
__global__ void cvtb_kernel(const float* __restrict__ bq,
                            const float* __restrict__ bk,
                            const float* __restrict__ bv) {
    const float* s = (blockIdx.x == 0) ? bq : (blockIdx.x == 1) ? bk : bv;
    g_b3[blockIdx.x * 256 + threadIdx.x] = s[threadIdx.x];
}

// ------------------------- bf16 HMMA GEMM (k=32 slices) ----------------------
// C[R][col] = sum_k A[R][k] * W[col][k].  CTA 128x128, 8 warps, 3-stage pipe.
// outQ mode: head-layout scatter. tensor 0 (Q): scaled by QSCALE, bf16.
//            tensor 1 (K): bf16.  tensor 2 (V): fp16.
__device__ __forceinline__ void stq(__nv_bfloat16* dst, int R, int col,
                                    float v0, float v1, int asHalf) {
    const int t  = col >> 8;
    const int cc = col & 255;
    const int b  = R >> 10, r = R & 1023;
    const int h  = r >> 7;
    const int dh = (r >> 2) & 31;
    const int jb = r & 3;
    const size_t off = (size_t)t * HSZ +
                       ((size_t)((b * 8 + h) * 32 + dh) << 10) + (jb * 256 + cc);
    *(u32*)&dst[off] = asHalf ? hf2(v0, v1) : bf2(v0, v1);
}

__global__ __launch_bounds__(256, 2) void gemm_bf16_kernel(
    const __nv_bfloat16* __restrict__ A,
    const __nv_bfloat16* __restrict__ Wb,
    const float* __restrict__ bias,
    __nv_bfloat16* __restrict__ outQ,
    float* __restrict__ outF,
    const float* __restrict__ Res)
{
    __shared__ __align__(16) __nv_bfloat16 As[3][5120];   // [128][40] per stage
    __shared__ __align__(16) __nv_bfloat16 Bs[3][5120];

    const int tid  = threadIdx.x;
    const int lane = tid & 31;
    const int w    = tid >> 5;
    const int g    = lane >> 2;
    const int tg   = lane & 3;
    const int bn   = blockIdx.x;
    const int bm   = blockIdx.y;
    const int warpM = (w & 3) * 32;
    const int warpN = (w >> 2) * 64;

    const int lrow = tid >> 1;           // tile row 0..127
    const int co   = (tid & 1) * 16;     // k offset 0 or 16 (8 el per cp16)
    const __nv_bfloat16* Ag = A  + (size_t)(bm * 128 + lrow) * 256 + co;
    const __nv_bfloat16* Bg = Wb + (size_t)(bn * 128 + lrow) * 256 + co;
    const u32 sA = (u32)__cvta_generic_to_shared(&As[0][lrow * 40 + co]);
    const u32 sB = (u32)__cvta_generic_to_shared(&Bs[0][lrow * 40 + co]);

    float acc[2][8][4];
#pragma unroll
    for (int i = 0; i < 2; i++)
#pragma unroll
        for (int j = 0; j < 8; j++)
#pragma unroll
            for (int r = 0; r < 4; r++) acc[i][j][r] = 0.f;

    // prologue: stages 0 and 1 (k0 = 0, 32)
    cp16(sA, Ag);                 cp16(sA + 16, Ag + 8);
    cp16(sB, Bg);                 cp16(sB + 16, Bg + 8);
    CP_COMMIT();
    cp16(sA + 10240, Ag + 32);    cp16(sA + 10240 + 16, Ag + 40);
    cp16(sB + 10240, Bg + 32);    cp16(sB + 10240 + 16, Bg + 40);
    CP_COMMIT();

    const int aRow = lane & 15;
    const int aCol = (lane >> 4) * 8;
    const int bRow = ((lane >> 4) << 3) + (lane & 7);
    const int bCol = ((lane >> 3) & 1) * 8;

    for (int ks = 0; ks < 8; ks++) {
        if (ks < 7) CP_WAIT1(); else CP_WAIT0();
        __syncthreads();

        const int buf = ks - (ks / 3) * 3;   // ks % 3
        const __nv_bfloat16* sa = As[buf];
        const __nv_bfloat16* sb = Bs[buf];
#pragma unroll
        for (int kc = 0; kc < 2; kc++) {
            const int kb = kc * 16;
            u32 a0[4], a1[4];
            ldsm4(a0[0], a0[1], a0[2], a0[3], sa + (warpM + aRow) * 40 + kb + aCol);
            ldsm4(a1[0], a1[1], a1[2], a1[3], sa + (warpM + 16 + aRow) * 40 + kb + aCol);
#pragma unroll
            for (int nf16 = 0; nf16 < 4; nf16++) {
                u32 b0, b1, b2, b3;
                ldsm4(b0, b1, b2, b3, sb + (warpN + nf16 * 16 + bRow) * 40 + kb + bCol);
                float* cl0 = acc[0][nf16 * 2];
                float* ch0 = acc[0][nf16 * 2 + 1];
                float* cl1 = acc[1][nf16 * 2];
                float* ch1 = acc[1][nf16 * 2 + 1];
                mma_bf16(cl0[0], cl0[1], cl0[2], cl0[3], a0[0], a0[1], a0[2], a0[3], b0, b1);
                mma_bf16(ch0[0], ch0[1], ch0[2], ch0[3], a0[0], a0[1], a0[2], a0[3], b2, b3);
                mma_bf16(cl1[0], cl1[1], cl1[2], cl1[3], a1[0], a1[1], a1[2], a1[3], b0, b1);
                mma_bf16(ch1[0], ch1[1], ch1[2], ch1[3], a1[0], a1[1], a1[2], a1[3], b2, b3);
            }
        }

        if (ks + 2 < 8) {   // issue after compute: stage (ks+2)%3 is free now
            const int nb = (ks + 2) - ((ks + 2) / 3) * 3;
            const int k0 = (ks + 2) * 32;
            cp16(sA + nb * 10240,      Ag + k0);
            cp16(sA + nb * 10240 + 16, Ag + k0 + 8);
            cp16(sB + nb * 10240,      Bg + k0);
            cp16(sB + nb * 10240 + 16, Bg + k0 + 8);
            CP_COMMIT();
        }
    }

    // epilogue
    const int tt      = (bn * 128) >> 8;            // tensor id in fused QKV
    const float scale = (outQ != nullptr && tt == 0) ? QSCALE : 1.0f;
    const int asHalf  = (tt == 2) ? 1 : 0;
#pragma unroll
    for (int mi = 0; mi < 2; mi++) {
        const int R0 = bm * 128 + warpM + mi * 16 + g;
#pragma unroll
        for (int nf = 0; nf < 8; nf++) {
            const int col = bn * 128 + warpN + nf * 8 + 2 * tg;
            const float2 bv = *(const float2*)&bias[col];
            const float v0 = (acc[mi][nf][0] + bv.x) * scale;
            const float v1 = (acc[mi][nf][1] + bv.y) * scale;
            const float v2 = (acc[mi][nf][2] + bv.x) * scale;
            const float v3 = (acc[mi][nf][3] + bv.y) * scale;
            if (outQ != nullptr) {
                stq(outQ, R0,     col, v0, v1, asHalf);
                stq(outQ, R0 + 8, col, v2, v3, asHalf);
            } else {
                const size_t i0 = (size_t)R0 * 256 + col;
                const size_t i1 = i0 + 8 * 256;
                const float2 r0 = *(const float2*)&Res[i0];
                const float2 r1 = *(const float2*)&Res[i1];
                *(float2*)&outF[i0] = make_float2(v0 + r0.x, v1 + r0.y);
                *(float2*)&outF[i1] = make_float2(v2 + r1.x, v3 + r1.y);
            }
        }
    }
}

// ------------------------------ Attention ------------------------------------
// CTA = (128-query tile, head, batch), 8 warps.  3-stage cp.async K/V pipe,
// ldmatrix feeds.  S = Q^T K in bf16 (Q pre-scaled to log2 domain),
// P = exp2(S + bias) via h2exp2 (f16x2 MUFU, pre-packed A-frags),
// denominators via all-ones f16 MMA, O += P V in f16 MMA (V stored fp16).
// Stage layout (bytes, per stage): K tile 4608 | V tile 4608  (stride 9216).
__global__ __launch_bounds__(256) void attn_kernel(const float* __restrict__ rel_bias) {
    extern __shared__ __align__(16) unsigned char smraw[];
    float* relb = (float*)smraw;                                  // 3972 floats
    __nv_bfloat16* Qs  = (__nv_bfloat16*)(smraw + 15888);         // [32][128]
    __nv_bfloat16* KVs = (__nv_bfloat16*)(smraw + 15888 + 8192);  // 3 stages

    const int tid  = threadIdx.x;
    const int w    = tid >> 5;
    const int lane = tid & 31;
    const int g    = lane >> 2;
    const int tg   = lane & 3;

    const int m0 = blockIdx.x * 128;
    const int h  = blockIdx.y;
    const int b  = blockIdx.z;
    const int bh = b * 8 + h;

    const __nv_bfloat16* qh = g_qkv + (size_t)bh * 32768;
    const __nv_bfloat16* kh = g_qkv + (size_t)HSZ     + (size_t)bh * 32768;
    const __nv_bfloat16* vh = g_qkv + (size_t)2 * HSZ + (size_t)bh * 32768;

    // K/V tile cp.async (per thread: one 16B chunk each)
    const int ld   = tid >> 3;
    const int noff = (tid & 7) * 8;
    const u32 sK = (u32)__cvta_generic_to_shared(KVs + ld * 72 + noff);
    const u32 sV = sK + 4608;
    const __nv_bfloat16* kg = kh + (size_t)ld * 1024 + noff;
    const __nv_bfloat16* vg = vh + (size_t)ld * 1024 + noff;

    cp16(sK, kg);             cp16(sV, vg);             CP_COMMIT();   // tile 0
    cp16(sK + 9216, kg + 64); cp16(sV + 9216, vg + 64); CP_COMMIT();   // tile 1

    // rel-bias table (pre-multiplied by log2e for exp2) + Q tile
    const float* rb = rel_bias + h * 3969;
    for (int i = tid; i < 3969; i += 256) relb[i] = rb[i] * 1.4426950408889634f;
    {
        const int d    = tid >> 3;
        const int moff = (tid & 7) * 16;
        const uint4* src = (const uint4*)(qh + (size_t)d * 1024 + m0 + moff);
        *(uint4*)(Qs + d * 128 + moff)     = src[0];
        *(uint4*)(Qs + d * 128 + moff + 8) = src[1];
    }
    __syncthreads();

    // Q A-fragments (once per CTA)
    const int mloc_lo = w * 16 + g;
    const int mloc_hi = mloc_lo + 8;
    u32 qa[2][4];
#pragma unroll
    for (int kc = 0; kc < 2; kc++) {
        const int k0 = kc * 16 + tg * 2;
        qa[kc][0] = pk2(&Qs[(k0 + 0) * 128 + mloc_lo], &Qs[(k0 + 1) * 128 + mloc_lo]);
        qa[kc][1] = pk2(&Qs[(k0 + 0) * 128 + mloc_hi], &Qs[(k0 + 1) * 128 + mloc_hi]);
        qa[kc][2] = pk2(&Qs[(k0 + 8) * 128 + mloc_lo], &Qs[(k0 + 9) * 128 + mloc_lo]);
        qa[kc][3] = pk2(&Qs[(k0 + 8) * 128 + mloc_hi], &Qs[(k0 + 9) * 128 + mloc_hi]);
    }

    const int m_lo = m0 + mloc_lo;
    const int m_hi = m_lo + 8;
    const int Clo  = 1984 - (m_lo >> 5) * 63 - (m_lo & 31);
    const int Chi  = 1984 - (m_hi >> 5) * 63 - (m_hi & 31);

    // ldmatrix lane addressing offsets
    const int i2 = lane >> 3;
    const int r8 = lane & 7;
    const int rowKb = ((i2 & 1) << 3) + r8;    // + kc*16  (trans, K)
    const int colKb = (i2 >> 1) << 3;          // + q4*16
    const int rowVb = ((i2 >> 1) << 3) + r8;   // + dfp*16 (non-trans, V)
    const int colVb = (i2 & 1) << 3;           // + f*16

    const u32 ONES = 0x3C003C00u;              // f16 {1.0, 1.0}

    float oc[4][4];
#pragma unroll
    for (int df = 0; df < 4; df++)
#pragma unroll
        for (int r = 0; r < 4; r++) oc[df][r] = 0.f;
    float rs4[4] = {0.f, 0.f, 0.f, 0.f};       // denominators via ones-MMA

    for (int nt = 0; nt < 16; nt++) {
        if (nt < 15) CP_WAIT1(); else CP_WAIT0();
        __syncthreads();

        const int st = nt - (nt / 3) * 3;   // nt % 3
        const __nv_bfloat16* Ksb = KVs + st * 4608;   // 4608 el = 9216 B stride
        const __nv_bfloat16* Vsb = Ksb + 2304;        // V is 4608 BYTES after K
        const int n0 = nt * 64;

        // ---- QK: S frags + exp2 epilogue -> pa (f16 pairs) -----------------
        u32 pa[4][4];
#pragma unroll
        for (int q4 = 0; q4 < 4; q4++) {
            u32 kf0[4], kf1[4];
            ldsm4t(kf0[0], kf0[1], kf0[2], kf0[3],
                   Ksb + (rowKb) * 72 + q4 * 16 + colKb);
            ldsm4t(kf1[0], kf1[1], kf1[2], kf1[3],
                   Ksb + (16 + rowKb) * 72 + q4 * 16 + colKb);
#pragma unroll
            for (int half = 0; half < 2; half++) {
                const int nf = q4 * 2 + half;
                float c0 = 0.f, c1 = 0.f, c2 = 0.f, c3 = 0.f;
                mma_bf16(c0, c1, c2, c3, qa[0][0], qa[0][1], qa[0][2], qa[0][3],
                         kf0[half * 2], kf0[half * 2 + 1]);
                mma_bf16(c0, c1, c2, c3, qa[1][0], qa[1][1], qa[1][2], qa[1][3],
                         kf1[half * 2], kf1[half * 2 + 1]);
                const int n1 = n0 + nf * 8 + tg * 2;
                const int n2 = n1 + 1;
                const int i1 = (n1 >> 5) * 63 + (n1 & 31);
                const int ix2 = (n2 >> 5) * 63 + (n2 & 31);
                // Q pre-scaled by 0.0625*log2e, relb pre-scaled by log2e
                const float e0 = c0 + relb[i1  + Clo];
                const float e1 = c1 + relb[ix2 + Clo];
                const float e2 = c2 + relb[i1  + Chi];
                const float e3 = c3 + relb[ix2 + Chi];
                const __half2 p01 = h2exp2(__floats2half2_rn(e0, e1));
                const __half2 p23 = h2exp2(__floats2half2_rn(e2, e3));
                if (half == 0) {
                    pa[q4][0] = *(const u32*)&p01;
                    pa[q4][1] = *(const u32*)&p23;
                } else {
                    pa[q4][2] = *(const u32*)&p01;
                    pa[q4][3] = *(const u32*)&p23;
                }
            }
        }

        // ---- PV: O += P V  (f16), denominators via ones-MMA -----------------
#pragma unroll
        for (int f = 0; f < 4; f++) {
            mma_f16(rs4[0], rs4[1], rs4[2], rs4[3],
                    pa[f][0], pa[f][1], pa[f][2], pa[f][3], ONES, ONES);
#pragma unroll
            for (int dfp = 0; dfp < 2; dfp++) {
                u32 vf[4];
                ldsm4(vf[0], vf[1], vf[2], vf[3],
                      Vsb + (dfp * 16 + rowVb) * 72 + f * 16 + colVb);
                const int df = dfp * 2;
                mma_f16(oc[df][0], oc[df][1], oc[df][2], oc[df][3],
                        pa[f][0], pa[f][1], pa[f][2], pa[f][3], vf[0], vf[1]);
                mma_f16(oc[df + 1][0], oc[df + 1][1], oc[df + 1][2], oc[df + 1][3],
                        pa[f][0], pa[f][1], pa[f][2], pa[f][3], vf[2], vf[3]);
            }
        }

        if (nt + 2 < 16) {   // issue after compute: stage (nt+2)%3 is free
            const int nb = (nt + 2) - ((nt + 2) / 3) * 3;
            cp16(sK + nb * 9216, kg + (nt + 2) * 64);
            cp16(sV + nb * 9216, vg + (nt + 2) * 64);
            CP_COMMIT();
        }
    }

    const float inv_lo = 1.0f / rs4[0];
    const float inv_hi = 1.0f / rs4[2];

    __nv_bfloat16* OL = g_ob + (size_t)b * PB;
    const int jblk = m0 >> 8;
    const int mclo = m_lo & 255;
    const int mchi = m_hi & 255;
#pragma unroll
    for (int df = 0; df < 4; df++) {
        const int d1 = df * 8 + tg * 2;
        const int d2 = d1 + 1;
        const int r1 = h * 128 + 4 * d1 + jblk;
        const int r2 = h * 128 + 4 * d2 + jblk;
        OL[r1 * 256 + mclo] = __float2bfloat16(oc[df][0] * inv_lo);
        OL[r2 * 256 + mclo] = __float2bfloat16(oc[df][1] * inv_lo);
        OL[r1 * 256 + mchi] = __float2bfloat16(oc[df][2] * inv_hi);
        OL[r2 * 256 + mchi] = __float2bfloat16(oc[df][3] * inv_hi);
    }
}

// ------------------------------ Launch --------------------------------------
extern "C" void kernel_launch(void* const* d_in, const int* in_sizes, int n_in,
                              void* d_out, int out_size) {
    const float* x        = (const float*)d_in[0];
    const float* ln_g     = (const float*)d_in[1];
    const float* ln_b     = (const float*)d_in[2];
    const float* wq       = (const float*)d_in[3];
    const float* bq       = (const float*)d_in[4];
    const float* wk       = (const float*)d_in[5];
    const float* bk       = (const float*)d_in[6];
    const float* wv       = (const float*)d_in[7];
    const float* bv       = (const float*)d_in[8];
    const float* wo       = (const float*)d_in[9];
    const float* bo       = (const float*)d_in[10];
    const float* rel_bias = (const float*)d_in[11];
    float* out = (float*)d_out;
    (void)in_sizes; (void)n_in; (void)out_size;

    __nv_bfloat16 *p_xnb, *p_ob, *p_qkv, *p_wb;
    float* p_b3;
    cudaGetSymbolAddress((void**)&p_xnb, g_xnb);
    cudaGetSymbolAddress((void**)&p_ob,  g_ob);
    cudaGetSymbolAddress((void**)&p_qkv, g_qkv);
    cudaGetSymbolAddress((void**)&p_wb,  g_wb);
    cudaGetSymbolAddress((void**)&p_b3,  g_b3);

    ln_kernel<<<dim3(4, BATCH), 256>>>(x, ln_g, ln_b);
    cvt_kernel<<<dim3(64, 4), 256>>>(wq, wk, wv, wo);
    cvtb_kernel<<<3, 256>>>(bq, bk, bv);

    // fused QKV: W = g_wb[0..3*65536) viewed as [768][256]
    gemm_bf16_kernel<<<dim3(6, 128), 256>>>(p_xnb, p_wb, p_b3, p_qkv, nullptr, nullptr);

    const int smem_bytes = 15888 + 8192 + 3 * 9216;   // 51728
    cudaFuncSetAttribute((const void*)attn_kernel,
                         cudaFuncAttributeMaxDynamicSharedMemorySize, smem_bytes);
    attn_kernel<<<dim3(8, 8, BATCH), 256, smem_bytes>>>(rel_bias);

    gemm_bf16_kernel<<<dim3(2, 128), 256>>>(p_ob, p_wb + 3 * 65536, bo, nullptr, out, x);
}

// round 17
// speedup vs baseline: 1.0154x; 1.0154x over previous
#include <cuda_runtime.h>
#include <cuda_bf16.h>

// ----------------------------------------------------------------------------
// RelativeAttention2d  (B=16, C=256, H=32 -> N=1024, HEADS=8, HS=32)
// Round: occupancy package — 128x64 GEMM tiles @3 CTAs/SM, 256-CTA LayerNorm,
//        attention = proven R15 path with Q pre-scaled to log2 domain.
// ----------------------------------------------------------------------------

namespace {
constexpr int BATCH = 16;
constexpr int PB    = 256 * 1024;
constexpr int HSZ   = BATCH * 8 * 32 * 1024;   // per-tensor head-layout elems
}

typedef unsigned int u32;

__device__ __nv_bfloat16 g_xnb[BATCH * PB];            // LN out  [16384][256]
__device__ __nv_bfloat16 g_ob [BATCH * PB];            // attn out [16384][256]
__device__ __nv_bfloat16 g_qkv[3 * HSZ];               // q,k,v  [b][h][d][tok]
__device__ __nv_bfloat16 g_wb[4 * 256 * 256];          // bf16 weights q,k,v,o
__device__ float         g_b3[768];                    // packed bq|bk|bv

// ------------------------------- helpers ------------------------------------
__device__ __forceinline__ u32 bf2(float a, float b) {
    __nv_bfloat162 t = __floats2bfloat162_rn(a, b);
    return *(u32*)&t;
}
__device__ __forceinline__ u32 pk2(const __nv_bfloat16* lo, const __nv_bfloat16* hi) {
    return (u32)*(const unsigned short*)lo | ((u32)*(const unsigned short*)hi << 16);
}
__device__ __forceinline__ void mma_bf16(float& c0, float& c1, float& c2, float& c3,
                                         u32 a0, u32 a1, u32 a2, u32 a3,
                                         u32 b0, u32 b1) {
    asm volatile(
        "mma.sync.aligned.m16n8k16.row.col.f32.bf16.bf16.f32 "
        "{%0,%1,%2,%3}, {%4,%5,%6,%7}, {%8,%9}, {%0,%1,%2,%3};"
        : "+f"(c0), "+f"(c1), "+f"(c2), "+f"(c3)
        : "r"(a0), "r"(a1), "r"(a2), "r"(a3), "r"(b0), "r"(b1));
}
__device__ __forceinline__ void ldsm4(u32& r0, u32& r1, u32& r2, u32& r3,
                                      const __nv_bfloat16* p) {
    u32 a = (u32)__cvta_generic_to_shared(p);
    asm volatile("ldmatrix.sync.aligned.m8n8.x4.shared.b16 {%0,%1,%2,%3}, [%4];"
                 : "=r"(r0), "=r"(r1), "=r"(r2), "=r"(r3) : "r"(a));
}
__device__ __forceinline__ void ldsm4t(u32& r0, u32& r1, u32& r2, u32& r3,
                                       const __nv_bfloat16* p) {
    u32 a = (u32)__cvta_generic_to_shared(p);
    asm volatile("ldmatrix.sync.aligned.m8n8.x4.trans.shared.b16 {%0,%1,%2,%3}, [%4];"
                 : "=r"(r0), "=r"(r1), "=r"(r2), "=r"(r3) : "r"(a));
}
__device__ __forceinline__ void cp16(u32 dst, const void* src) {
    asm volatile("cp.async.cg.shared.global [%0], [%1], 16;" :: "r"(dst), "l"(src));
}
#define CP_COMMIT()  asm volatile("cp.async.commit_group;")
#define CP_WAIT1()   asm volatile("cp.async.wait_group 1;")
#define CP_WAIT0()   asm volatile("cp.async.wait_group 0;")

// Q pre-scale: 1/sqrt(256) folded with log2(e) so softmax uses exp2 directly.
#define QSCALE 0.0901941142223433f

// ------------------------------ LayerNorm (-> bf16) --------------------------
// grid(16, BATCH), block 256.  4 threads per spatial position (64 channels
// each), same-warp shfl reduction.  256 CTAs -> full-chip residency.
__global__ __launch_bounds__(256) void ln_kernel(const float* __restrict__ x,
                                                 const float* __restrict__ gamma,
                                                 const float* __restrict__ beta) {
    __shared__ float sg[256];
    __shared__ float sb[256];
    const int tid = threadIdx.x;
    sg[tid] = gamma[tid];
    sb[tid] = beta[tid];
    __syncthreads();

    const int b  = blockIdx.y;
    const int p  = blockIdx.x * 64 + (tid >> 2);
    const int c0 = (tid & 3) * 64;
    const float* xb = x + (size_t)b * PB + p;

    float s = 0.f, ss = 0.f;
#pragma unroll 16
    for (int i = 0; i < 64; i++) {
        const float v = xb[(c0 + i) * 1024];
        s += v;
        ss += v * v;
    }
    s  += __shfl_xor_sync(0xffffffffu, s, 1);
    s  += __shfl_xor_sync(0xffffffffu, s, 2);
    ss += __shfl_xor_sync(0xffffffffu, ss, 1);
    ss += __shfl_xor_sync(0xffffffffu, ss, 2);

    const float mu  = s * (1.0f / 256.0f);
    const float var = ss * (1.0f / 256.0f) - mu * mu;
    const float r   = rsqrtf(var + 1e-5f);

    __nv_bfloat16* ob = g_xnb + (size_t)b * PB + p;
#pragma unroll 16
    for (int i = 0; i < 64; i++) {
        const float v = xb[(c0 + i) * 1024];
        ob[(c0 + i) * 1024] = __float2bfloat16((v - mu) * r * sg[(c0 + i)] + sb[(c0 + i)]);
    }
}

// ---------------- weight fp32->bf16 + bias packing ---------------------------
__global__ __launch_bounds__(256) void cvt_kernel(const float* __restrict__ w0,
                                                  const float* __restrict__ w1,
                                                  const float* __restrict__ w2,
                                                  const float* __restrict__ w3) {
    const float* src = (blockIdx.y == 0) ? w0 : (blockIdx.y == 1) ? w1
                     : (blockIdx.y == 2) ? w2 : w3;
    __nv_bfloat16* dst = g_wb + (size_t)blockIdx.y * 65536;
    const int i = (blockIdx.x * 256 + threadIdx.x) * 4;
    const float4 v = *(const float4*)&src[i];
    uint2 st;
    st.x = bf2(v.x, v.y);
    st.y = bf2(v.z, v.w);
    *(uint2*)&dst[i] = st;
}
__global__ void cvtb_kernel(const float* __restrict__ bq,
                            const float* __restrict__ bk,
                            const float* __restrict__ bv) {
    const float* s = (blockIdx.x == 0) ? bq : (blockIdx.x == 1) ? bk : bv;
    g_b3[blockIdx.x * 256 + threadIdx.x] = s[threadIdx.x];
}

// ------------------------- bf16 HMMA GEMM (128x64 tiles) ---------------------
// C[R][col] = sum_k A[R][k] * W[col][k].  CTA 128x64, 8 warps (4M x 2N),
// 3-stage cp.async pipe, 8 k-slices of 32.  3 CTAs/SM (launch_bounds).
// outQ mode: head-layout scatter; tensor 0 (Q) pre-scaled by QSCALE.
__device__ __forceinline__ void stq(__nv_bfloat16* dst, int R, int col,
                                    float v0, float v1) {
    const int t  = col >> 8;
    const int cc = col & 255;
    const int b  = R >> 10, r = R & 1023;
    const int h  = r >> 7;
    const int dh = (r >> 2) & 31;
    const int jb = r & 3;
    const size_t off = (size_t)t * HSZ +
                       ((size_t)((b * 8 + h) * 32 + dh) << 10) + (jb * 256 + cc);
    *(u32*)&dst[off] = bf2(v0, v1);
}

__global__ __launch_bounds__(256, 3) void gemm_bf16_kernel(
    const __nv_bfloat16* __restrict__ A,
    const __nv_bfloat16* __restrict__ Wb,
    const float* __restrict__ bias,
    __nv_bfloat16* __restrict__ outQ,
    float* __restrict__ outF,
    const float* __restrict__ Res)
{
    __shared__ __align__(16) __nv_bfloat16 As[3][5120];   // [128][40] per stage
    __shared__ __align__(16) __nv_bfloat16 Bs[3][2560];   // [64][40]  per stage

    const int tid  = threadIdx.x;
    const int lane = tid & 31;
    const int w    = tid >> 5;
    const int g    = lane >> 2;
    const int tg   = lane & 3;
    const int bn   = blockIdx.x;
    const int bm   = blockIdx.y;
    const int warpM = (w & 3) * 32;
    const int warpN = (w >> 2) * 32;

    // A loader: 128 rows x 32 k-els via 2 cp16/thread
    const int lrow = tid >> 1;
    const int co   = (tid & 1) * 16;
    const __nv_bfloat16* Ag = A + (size_t)(bm * 128 + lrow) * 256 + co;
    const u32 sA = (u32)__cvta_generic_to_shared(&As[0][lrow * 40 + co]);
    // B loader: 64 rows x 32 k-els via 1 cp16/thread
    const int rowB = tid >> 2;
    const int coB  = (tid & 3) * 8;
    const __nv_bfloat16* Bg = Wb + (size_t)(bn * 64 + rowB) * 256 + coB;
    const u32 sB = (u32)__cvta_generic_to_shared(&Bs[0][rowB * 40 + coB]);

    float acc[2][4][4];
#pragma unroll
    for (int i = 0; i < 2; i++)
#pragma unroll
        for (int j = 0; j < 4; j++)
#pragma unroll
            for (int r = 0; r < 4; r++) acc[i][j][r] = 0.f;

    // prologue: stages 0 and 1 (k0 = 0, 32)
    cp16(sA, Ag);              cp16(sA + 16, Ag + 8);
    cp16(sB, Bg);
    CP_COMMIT();
    cp16(sA + 10240, Ag + 32); cp16(sA + 10240 + 16, Ag + 40);
    cp16(sB + 5120, Bg + 32);
    CP_COMMIT();

    const int aRow = lane & 15;
    const int aCol = (lane >> 4) * 8;
    const int bRow = ((lane >> 4) << 3) + (lane & 7);
    const int bCol = ((lane >> 3) & 1) * 8;

    for (int ks = 0; ks < 8; ks++) {
        if (ks < 7) CP_WAIT1(); else CP_WAIT0();
        __syncthreads();

        const int buf = ks - (ks / 3) * 3;   // ks % 3
        const __nv_bfloat16* sa = As[buf];
        const __nv_bfloat16* sb = Bs[buf];
#pragma unroll
        for (int kc = 0; kc < 2; kc++) {
            const int kb = kc * 16;
            u32 a0[4], a1[4];
            ldsm4(a0[0], a0[1], a0[2], a0[3], sa + (warpM + aRow) * 40 + kb + aCol);
            ldsm4(a1[0], a1[1], a1[2], a1[3], sa + (warpM + 16 + aRow) * 40 + kb + aCol);
#pragma unroll
            for (int nf16 = 0; nf16 < 2; nf16++) {
                u32 b0, b1, b2, b3;
                ldsm4(b0, b1, b2, b3, sb + (warpN + nf16 * 16 + bRow) * 40 + kb + bCol);
                float* cl0 = acc[0][nf16 * 2];
                float* ch0 = acc[0][nf16 * 2 + 1];
                float* cl1 = acc[1][nf16 * 2];
                float* ch1 = acc[1][nf16 * 2 + 1];
                mma_bf16(cl0[0], cl0[1], cl0[2], cl0[3], a0[0], a0[1], a0[2], a0[3], b0, b1);
                mma_bf16(ch0[0], ch0[1], ch0[2], ch0[3], a0[0], a0[1], a0[2], a0[3], b2, b3);
                mma_bf16(cl1[0], cl1[1], cl1[2], cl1[3], a1[0], a1[1], a1[2], a1[3], b0, b1);
                mma_bf16(ch1[0], ch1[1], ch1[2], ch1[3], a1[0], a1[1], a1[2], a1[3], b2, b3);
            }
        }

        if (ks + 2 < 8) {   // issue after compute: stage (ks+2)%3 is free now
            const int nb = (ks + 2) - ((ks + 2) / 3) * 3;
            const int k0 = (ks + 2) * 32;
            cp16(sA + nb * 10240,      Ag + k0);
            cp16(sA + nb * 10240 + 16, Ag + k0 + 8);
            cp16(sB + nb * 5120,       Bg + k0);
            CP_COMMIT();
        }
    }

    // epilogue
    const int tt      = (bn * 64) >> 8;             // tensor id in fused QKV
    const float scale = (outQ != nullptr && tt == 0) ? QSCALE : 1.0f;
#pragma unroll
    for (int mi = 0; mi < 2; mi++) {
        const int R0 = bm * 128 + warpM + mi * 16 + g;
#pragma unroll
        for (int nf = 0; nf < 4; nf++) {
            const int col = bn * 64 + warpN + nf * 8 + 2 * tg;
            const float2 bv = *(const float2*)&bias[col];
            const float v0 = (acc[mi][nf][0] + bv.x) * scale;
            const float v1 = (acc[mi][nf][1] + bv.y) * scale;
            const float v2 = (acc[mi][nf][2] + bv.x) * scale;
            const float v3 = (acc[mi][nf][3] + bv.y) * scale;
            if (outQ != nullptr) {
                stq(outQ, R0,     col, v0, v1);
                stq(outQ, R0 + 8, col, v2, v3);
            } else {
                const size_t i0 = (size_t)R0 * 256 + col;
                const size_t i1 = i0 + 8 * 256;
                const float2 r0 = *(const float2*)&Res[i0];
                const float2 r1 = *(const float2*)&Res[i1];
                *(float2*)&outF[i0] = make_float2(v0 + r0.x, v1 + r0.y);
                *(float2*)&outF[i1] = make_float2(v2 + r1.x, v3 + r1.y);
            }
        }
    }
}

// ------------------------------ Attention (bf16 HMMA) ------------------------
// CTA = (128-query tile, head, batch), 8 warps.  3-stage cp.async K/V pipe,
// ldmatrix feeds, analytic rel-bias (table pre-scaled by log2e), exp2f.
// Q arrives pre-scaled by 0.0625*log2e, so the exp argument is a plain add.
// Stage layout (bytes, per stage): K tile 4608 | V tile 4608  (stride 9216).
__global__ __launch_bounds__(256) void attn_kernel(const float* __restrict__ rel_bias) {
    extern __shared__ __align__(16) unsigned char smraw[];
    float* relb = (float*)smraw;                                  // 3972 floats
    __nv_bfloat16* Qs  = (__nv_bfloat16*)(smraw + 15888);         // [32][128]
    __nv_bfloat16* KVs = (__nv_bfloat16*)(smraw + 15888 + 8192);  // 3 stages

    const int tid  = threadIdx.x;
    const int w    = tid >> 5;
    const int lane = tid & 31;
    const int g    = lane >> 2;
    const int tg   = lane & 3;

    const int m0 = blockIdx.x * 128;
    const int h  = blockIdx.y;
    const int b  = blockIdx.z;
    const int bh = b * 8 + h;

    const __nv_bfloat16* qh = g_qkv + (size_t)bh * 32768;
    const __nv_bfloat16* kh = g_qkv + (size_t)HSZ     + (size_t)bh * 32768;
    const __nv_bfloat16* vh = g_qkv + (size_t)2 * HSZ + (size_t)bh * 32768;

    // K/V tile cp.async (per thread: one 16B chunk each)
    const int ld   = tid >> 3;
    const int noff = (tid & 7) * 8;
    const u32 sK = (u32)__cvta_generic_to_shared(KVs + ld * 72 + noff);
    const u32 sV = sK + 4608;
    const __nv_bfloat16* kg = kh + (size_t)ld * 1024 + noff;
    const __nv_bfloat16* vg = vh + (size_t)ld * 1024 + noff;

    cp16(sK, kg);             cp16(sV, vg);             CP_COMMIT();   // tile 0
    cp16(sK + 9216, kg + 64); cp16(sV + 9216, vg + 64); CP_COMMIT();   // tile 1

    // rel-bias table (pre-multiplied by log2e for exp2f) + Q tile
    const float* rb = rel_bias + h * 3969;
    for (int i = tid; i < 3969; i += 256) relb[i] = rb[i] * 1.4426950408889634f;
    {
        const int d    = tid >> 3;
        const int moff = (tid & 7) * 16;
        const uint4* src = (const uint4*)(qh + (size_t)d * 1024 + m0 + moff);
        *(uint4*)(Qs + d * 128 + moff)     = src[0];
        *(uint4*)(Qs + d * 128 + moff + 8) = src[1];
    }
    __syncthreads();

    // Q A-fragments (once per CTA)
    const int mloc_lo = w * 16 + g;
    const int mloc_hi = mloc_lo + 8;
    u32 qa[2][4];
#pragma unroll
    for (int kc = 0; kc < 2; kc++) {
        const int k0 = kc * 16 + tg * 2;
        qa[kc][0] = pk2(&Qs[(k0 + 0) * 128 + mloc_lo], &Qs[(k0 + 1) * 128 + mloc_lo]);
        qa[kc][1] = pk2(&Qs[(k0 + 0) * 128 + mloc_hi], &Qs[(k0 + 1) * 128 + mloc_hi]);
        qa[kc][2] = pk2(&Qs[(k0 + 8) * 128 + mloc_lo], &Qs[(k0 + 9) * 128 + mloc_lo]);
        qa[kc][3] = pk2(&Qs[(k0 + 8) * 128 + mloc_hi], &Qs[(k0 + 9) * 128 + mloc_hi]);
    }

    const int m_lo = m0 + mloc_lo;
    const int m_hi = m_lo + 8;
    const int Clo  = 1984 - (m_lo >> 5) * 63 - (m_lo & 31);
    const int Chi  = 1984 - (m_hi >> 5) * 63 - (m_hi & 31);

    // ldmatrix lane addressing offsets
    const int i2 = lane >> 3;
    const int r8 = lane & 7;
    const int rowKb = ((i2 & 1) << 3) + r8;    // + kc*16  (trans, K)
    const int colKb = (i2 >> 1) << 3;          // + q4*16
    const int rowVb = ((i2 >> 1) << 3) + r8;   // + dfp*16 (non-trans, V)
    const int colVb = (i2 & 1) << 3;           // + f*16

    float oc[4][4];
#pragma unroll
    for (int df = 0; df < 4; df++)
#pragma unroll
        for (int r = 0; r < 4; r++) oc[df][r] = 0.f;
    float rs_lo = 0.f, rs_hi = 0.f;

    for (int nt = 0; nt < 16; nt++) {
        if (nt < 15) CP_WAIT1(); else CP_WAIT0();
        __syncthreads();

        const int st = nt - (nt / 3) * 3;   // nt % 3
        const __nv_bfloat16* Ksb = KVs + st * 4608;   // 4608 el = 9216 B stride
        const __nv_bfloat16* Vsb = Ksb + 2304;        // V is 4608 BYTES after K
        const int n0 = nt * 64;

        // ---- QK: S frags + exp2 epilogue -> pa ------------------------------
        u32 pa[4][4];
#pragma unroll
        for (int q4 = 0; q4 < 4; q4++) {
            u32 kf0[4], kf1[4];
            ldsm4t(kf0[0], kf0[1], kf0[2], kf0[3],
                   Ksb + (rowKb) * 72 + q4 * 16 + colKb);
            ldsm4t(kf1[0], kf1[1], kf1[2], kf1[3],
                   Ksb + (16 + rowKb) * 72 + q4 * 16 + colKb);
#pragma unroll
            for (int half = 0; half < 2; half++) {
                const int nf = q4 * 2 + half;
                float c0 = 0.f, c1 = 0.f, c2 = 0.f, c3 = 0.f;
                mma_bf16(c0, c1, c2, c3, qa[0][0], qa[0][1], qa[0][2], qa[0][3],
                         kf0[half * 2], kf0[half * 2 + 1]);
                mma_bf16(c0, c1, c2, c3, qa[1][0], qa[1][1], qa[1][2], qa[1][3],
                         kf1[half * 2], kf1[half * 2 + 1]);
                const int n1 = n0 + nf * 8 + tg * 2;
                const int n2 = n1 + 1;
                const int i1 = (n1 >> 5) * 63 + (n1 & 31);
                const int ix2 = (n2 >> 5) * 63 + (n2 & 31);
                // Q pre-scaled by 0.0625*log2e, relb pre-scaled by log2e
                const float p0 = exp2f(c0 + relb[i1  + Clo]);
                const float p1 = exp2f(c1 + relb[ix2 + Clo]);
                const float p2 = exp2f(c2 + relb[i1  + Chi]);
                const float p3 = exp2f(c3 + relb[ix2 + Chi]);
                rs_lo += p0 + p1;
                rs_hi += p2 + p3;
                const int f = nf >> 1;
                if ((nf & 1) == 0) {
                    pa[f][0] = bf2(p0, p1);
                    pa[f][1] = bf2(p2, p3);
                } else {
                    pa[f][2] = bf2(p0, p1);
                    pa[f][3] = bf2(p2, p3);
                }
            }
        }

        // ---- PV: O += P V ---------------------------------------------------
#pragma unroll
        for (int f = 0; f < 4; f++) {
#pragma unroll
            for (int dfp = 0; dfp < 2; dfp++) {
                u32 vf[4];
                ldsm4(vf[0], vf[1], vf[2], vf[3],
                      Vsb + (dfp * 16 + rowVb) * 72 + f * 16 + colVb);
                const int df = dfp * 2;
                mma_bf16(oc[df][0], oc[df][1], oc[df][2], oc[df][3],
                         pa[f][0], pa[f][1], pa[f][2], pa[f][3], vf[0], vf[1]);
                mma_bf16(oc[df + 1][0], oc[df + 1][1], oc[df + 1][2], oc[df + 1][3],
                         pa[f][0], pa[f][1], pa[f][2], pa[f][3], vf[2], vf[3]);
            }
        }

        if (nt + 2 < 16) {   // issue after compute: stage (nt+2)%3 is free
            const int nb = (nt + 2) - ((nt + 2) / 3) * 3;
            cp16(sK + nb * 9216, kg + (nt + 2) * 64);
            cp16(sV + nb * 9216, vg + (nt + 2) * 64);
            CP_COMMIT();
        }
    }

    rs_lo += __shfl_xor_sync(0xffffffffu, rs_lo, 1);
    rs_lo += __shfl_xor_sync(0xffffffffu, rs_lo, 2);
    rs_hi += __shfl_xor_sync(0xffffffffu, rs_hi, 1);
    rs_hi += __shfl_xor_sync(0xffffffffu, rs_hi, 2);
    const float inv_lo = 1.0f / rs_lo;
    const float inv_hi = 1.0f / rs_hi;

    __nv_bfloat16* OL = g_ob + (size_t)b * PB;
    const int jblk = m0 >> 8;
    const int mclo = m_lo & 255;
    const int mchi = m_hi & 255;
#pragma unroll
    for (int df = 0; df < 4; df++) {
        const int d1 = df * 8 + tg * 2;
        const int d2 = d1 + 1;
        const int r1 = h * 128 + 4 * d1 + jblk;
        const int r2 = h * 128 + 4 * d2 + jblk;
        OL[r1 * 256 + mclo] = __float2bfloat16(oc[df][0] * inv_lo);
        OL[r2 * 256 + mclo] = __float2bfloat16(oc[df][1] * inv_lo);
        OL[r1 * 256 + mchi] = __float2bfloat16(oc[df][2] * inv_hi);
        OL[r2 * 256 + mchi] = __float2bfloat16(oc[df][3] * inv_hi);
    }
}

// ------------------------------ Launch --------------------------------------
extern "C" void kernel_launch(void* const* d_in, const int* in_sizes, int n_in,
                              void* d_out, int out_size) {
    const float* x        = (const float*)d_in[0];
    const float* ln_g     = (const float*)d_in[1];
    const float* ln_b     = (const float*)d_in[2];
    const float* wq       = (const float*)d_in[3];
    const float* bq       = (const float*)d_in[4];
    const float* wk       = (const float*)d_in[5];
    const float* bk       = (const float*)d_in[6];
    const float* wv       = (const float*)d_in[7];
    const float* bv       = (const float*)d_in[8];
    const float* wo       = (const float*)d_in[9];
    const float* bo       = (const float*)d_in[10];
    const float* rel_bias = (const float*)d_in[11];
    float* out = (float*)d_out;
    (void)in_sizes; (void)n_in; (void)out_size;

    __nv_bfloat16 *p_xnb, *p_ob, *p_qkv, *p_wb;
    float* p_b3;
    cudaGetSymbolAddress((void**)&p_xnb, g_xnb);
    cudaGetSymbolAddress((void**)&p_ob,  g_ob);
    cudaGetSymbolAddress((void**)&p_qkv, g_qkv);
    cudaGetSymbolAddress((void**)&p_wb,  g_wb);
    cudaGetSymbolAddress((void**)&p_b3,  g_b3);

    ln_kernel<<<dim3(16, BATCH), 256>>>(x, ln_g, ln_b);
    cvt_kernel<<<dim3(64, 4), 256>>>(wq, wk, wv, wo);
    cvtb_kernel<<<3, 256>>>(bq, bk, bv);

    // fused QKV: W = g_wb[0..3*65536) viewed as [768][256]
    gemm_bf16_kernel<<<dim3(12, 128), 256>>>(p_xnb, p_wb, p_b3, p_qkv, nullptr, nullptr);

    const int smem_bytes = 15888 + 8192 + 3 * 9216;   // 51728
    cudaFuncSetAttribute((const void*)attn_kernel,
                         cudaFuncAttributeMaxDynamicSharedMemorySize, smem_bytes);
    attn_kernel<<<dim3(8, 8, BATCH), 256, smem_bytes>>>(rel_bias);

    gemm_bf16_kernel<<<dim3(4, 128), 256>>>(p_ob, p_wb + 3 * 65536, bo, nullptr, out, x);
}